// round 1
// baseline (speedup 1.0000x reference)
#include <cuda_runtime.h>
#include <cstdint>

// ---------------------------------------------------------------------------
// KWTA: per-sample k-th-largest threshold + masked NHWC->NCHW transpose.
// x: (32, 56, 56, 256) fp32.  dim = 802816, k = ceil(0.2*dim) = 160564.
// Output layout (per reference's transpose->reshape): out[b][c][h][w] = masked x[b][h][w][c]
// ---------------------------------------------------------------------------

#define B          32
#define HW         3136            // 56*56
#define C          256
#define DIM        802816          // HW*C
#define DIM4       200704          // DIM/4
#define KSEL       160564u
#define NBINS      2048            // top-11-bit histogram
#define CAP        131072          // candidate buffer per sample (safe bound ~4.5x expected)
#define HBLOCKS    98              // per-sample blocks for hist/compact (98*2048 float4 = DIM4)

__device__ unsigned g_hist[B * NBINS];
__device__ unsigned g_cnt[B];
__device__ unsigned g_bin[B];
__device__ unsigned g_kprime[B];
__device__ unsigned g_cand[B * CAP];   // 16 MB static scratch
__device__ float    g_thresh[B];

__device__ __forceinline__ unsigned f2key(float f) {
    unsigned u = __float_as_uint(f);
    // order-preserving: larger float -> larger key
    return (u & 0x80000000u) ? ~u : (u | 0x80000000u);
}

// ---- 1. zero scratch -------------------------------------------------------
__global__ void zero_kernel() {
    int i = blockIdx.x * blockDim.x + threadIdx.x;
    if (i < B * NBINS) g_hist[i] = 0;
    if (i < B) g_cnt[i] = 0;
}

// ---- 2. coarse histogram (top 11 bits of key) ------------------------------
__global__ __launch_bounds__(256) void hist_kernel(const float4* __restrict__ x) {
    __shared__ unsigned sh[NBINS];
    int tid = threadIdx.x;
    #pragma unroll
    for (int i = tid; i < NBINS; i += 256) sh[i] = 0;
    __syncthreads();

    int s = blockIdx.y;
    const float4* p = x + (size_t)s * DIM4 + (size_t)blockIdx.x * 2048;
    #pragma unroll
    for (int it = 0; it < 8; it++) {
        float4 v = p[tid + it * 256];
        atomicAdd(&sh[f2key(v.x) >> 21], 1u);
        atomicAdd(&sh[f2key(v.y) >> 21], 1u);
        atomicAdd(&sh[f2key(v.z) >> 21], 1u);
        atomicAdd(&sh[f2key(v.w) >> 21], 1u);
    }
    __syncthreads();
    for (int i = tid; i < NBINS; i += 256) {
        unsigned c = sh[i];
        if (c) atomicAdd(&g_hist[s * NBINS + i], c);
    }
}

// ---- 3. find target bin + residual k' per sample ---------------------------
__global__ void scan_kernel() {
    __shared__ unsigned sh[NBINS];
    int s = blockIdx.x;
    int tid = threadIdx.x;
    for (int i = tid; i < NBINS; i += blockDim.x) sh[i] = g_hist[s * NBINS + i];
    __syncthreads();
    if (tid == 0) {
        unsigned cum = 0;
        int b = NBINS - 1;
        for (; b >= 0; b--) {
            cum += sh[b];
            if (cum >= KSEL) break;
        }
        if (b < 0) b = 0; // cannot happen: cum over all bins == DIM > KSEL
        g_bin[s] = (unsigned)b;
        g_kprime[s] = KSEL - (cum - sh[b]);
    }
}

// ---- 4. compact candidate keys (elements in target bin) --------------------
__global__ __launch_bounds__(256) void compact_kernel(const float4* __restrict__ x) {
    int s = blockIdx.y;
    unsigned bin = g_bin[s];
    int tid = threadIdx.x;
    int lane = tid & 31;
    const float4* p = x + (size_t)s * DIM4 + (size_t)blockIdx.x * 2048;

    #pragma unroll
    for (int it = 0; it < 8; it++) {
        float4 v = p[tid + it * 256];
        unsigned keys[4] = { f2key(v.x), f2key(v.y), f2key(v.z), f2key(v.w) };
        #pragma unroll
        for (int q = 0; q < 4; q++) {
            unsigned key = keys[q];
            bool m = (key >> 21) == bin;
            unsigned bal = __ballot_sync(0xffffffffu, m);
            if (m) {
                int leader = __ffs(bal) - 1;
                unsigned base = 0;
                if (lane == leader) base = atomicAdd(&g_cnt[s], (unsigned)__popc(bal));
                base = __shfl_sync(bal, base, leader);
                unsigned pos = base + (unsigned)__popc(bal & ((1u << lane) - 1u));
                if (pos < CAP) g_cand[(size_t)s * CAP + pos] = key;
            }
        }
    }
}

// ---- 5. exact radix select over candidates (3 x 7-bit passes) --------------
__global__ __launch_bounds__(256) void select_kernel() {
    __shared__ unsigned sh[128];
    __shared__ unsigned s_prefix, s_kp;
    int s = blockIdx.x;
    int tid = threadIdx.x;
    unsigned n = g_cnt[s];
    if (n > CAP) n = CAP;
    unsigned prefix = g_bin[s] << 21;
    unsigned kp = g_kprime[s];

    #pragma unroll
    for (int pass = 0; pass < 3; pass++) {
        int shift = 14 - pass * 7;
        unsigned pmask = 0xFFFFFFFFu << (shift + 7); // bits above current digit
        for (int i = tid; i < 128; i += 256) sh[i] = 0;
        __syncthreads();
        for (unsigned i = tid; i < n; i += 256) {
            unsigned key = g_cand[(size_t)s * CAP + i];
            if ((key & pmask) == prefix)
                atomicAdd(&sh[(key >> shift) & 127u], 1u);
        }
        __syncthreads();
        if (tid == 0) {
            unsigned cum = 0;
            int d = 127;
            for (; d >= 0; d--) {
                cum += sh[d];
                if (cum >= kp) break;
            }
            if (d < 0) d = 0;
            s_kp = kp - (cum - sh[d]);
            s_prefix = prefix | ((unsigned)d << shift);
        }
        __syncthreads();
        prefix = s_prefix;
        kp = s_kp;
        __syncthreads();
    }

    if (tid == 0) {
        unsigned key = prefix;
        unsigned u = (key & 0x80000000u) ? (key & 0x7FFFFFFFu) : ~key;
        g_thresh[s] = __uint_as_float(u);
    }
}

// ---- 6. masked transpose: (hw, c) -> (c, hw), fully coalesced --------------
__global__ __launch_bounds__(256) void mask_transpose_kernel(const float* __restrict__ x,
                                                             float* __restrict__ out) {
    __shared__ float tile[32][33];
    int b = blockIdx.z;
    float th = g_thresh[b];
    int c0 = blockIdx.x * 32;
    int hw0 = blockIdx.y * 32;
    const float* xin = x + (size_t)b * DIM;
    float* o = out + (size_t)b * DIM;
    int tx = threadIdx.x, ty = threadIdx.y;

    #pragma unroll
    for (int j = 0; j < 32; j += 8) {
        float v = xin[(size_t)(hw0 + ty + j) * C + (c0 + tx)];
        tile[ty + j][tx] = (v >= th) ? v : 0.0f;
    }
    __syncthreads();
    #pragma unroll
    for (int j = 0; j < 32; j += 8) {
        o[(size_t)(c0 + ty + j) * HW + (hw0 + tx)] = tile[tx][ty + j];
    }
}

// ---------------------------------------------------------------------------
extern "C" void kernel_launch(void* const* d_in, const int* in_sizes, int n_in,
                              void* d_out, int out_size) {
    (void)in_sizes; (void)n_in; (void)out_size;
    const float* x = (const float*)d_in[0];
    float* out = (float*)d_out;

    zero_kernel<<<(B * NBINS + 255) / 256, 256>>>();

    dim3 hgrid(HBLOCKS, B);
    hist_kernel<<<hgrid, 256>>>((const float4*)x);

    scan_kernel<<<B, 256>>>();

    compact_kernel<<<hgrid, 256>>>((const float4*)x);

    select_kernel<<<B, 256>>>();

    dim3 tblk(32, 8);
    dim3 tgrid(C / 32, HW / 32, B);
    mask_transpose_kernel<<<tgrid, tblk>>>(x, out);
}

// round 3
// speedup vs baseline: 3.8177x; 3.8177x over previous
#include <cuda_runtime.h>
#include <cstdint>

// ---------------------------------------------------------------------------
// KWTA: per-sample k-th-largest threshold + masked NHWC->NCHW transpose.
// x: (32, 56, 56, 256) fp32.  dim = 802816, k = ceil(0.2*dim) = 160564.
// out[b][c][h][w] = masked x[b][h][w][c]
// ---------------------------------------------------------------------------

#define B          32
#define HW         3136            // 56*56
#define C          256
#define DIM        802816          // HW*C
#define DIM4       200704          // DIM/4
#define KSEL       160564u
#define NBINS      2048            // top-11-bit histogram
#define CAP        131072          // candidate buffer per sample
#define HBLOCKS    98              // 98*2048 float4 = DIM4 per sample

__device__ unsigned g_hist[B * NBINS];
__device__ unsigned g_cnt[B];
__device__ unsigned g_bin[B];
__device__ unsigned g_kprime[B];
__device__ unsigned g_cand[B * CAP];
__device__ float    g_thresh[B];

__device__ __forceinline__ unsigned f2key(float f) {
    unsigned u = __float_as_uint(f);
    return (u & 0x80000000u) ? ~u : (u | 0x80000000u);
}

// ---- 1. zero scratch -------------------------------------------------------
__global__ void zero_kernel() {
    int i = blockIdx.x * blockDim.x + threadIdx.x;
    if (i < B * NBINS) g_hist[i] = 0;
    if (i < B) g_cnt[i] = 0;
}

// ---- 2. coarse histogram (top 11 bits of key) ------------------------------
__global__ __launch_bounds__(256) void hist_kernel(const float4* __restrict__ x) {
    __shared__ unsigned sh[NBINS];
    int tid = threadIdx.x;
    #pragma unroll
    for (int i = tid; i < NBINS; i += 256) sh[i] = 0;
    __syncthreads();

    int s = blockIdx.y;
    const float4* p = x + (size_t)s * DIM4 + (size_t)blockIdx.x * 2048;
    #pragma unroll
    for (int it = 0; it < 8; it++) {
        float4 v = p[tid + it * 256];
        atomicAdd(&sh[f2key(v.x) >> 21], 1u);
        atomicAdd(&sh[f2key(v.y) >> 21], 1u);
        atomicAdd(&sh[f2key(v.z) >> 21], 1u);
        atomicAdd(&sh[f2key(v.w) >> 21], 1u);
    }
    __syncthreads();
    for (int i = tid; i < NBINS; i += 256) {
        unsigned c = sh[i];
        if (c) atomicAdd(&g_hist[s * NBINS + i], c);
    }
}

// ---- 3. find target bin + residual k' per sample ---------------------------
__global__ void scan_kernel() {
    __shared__ unsigned sh[NBINS];
    int s = blockIdx.x;
    int tid = threadIdx.x;
    for (int i = tid; i < NBINS; i += blockDim.x) sh[i] = g_hist[s * NBINS + i];
    __syncthreads();
    if (tid == 0) {
        unsigned cum = 0;
        int b = NBINS - 1;
        for (; b >= 0; b--) {
            cum += sh[b];
            if (cum >= KSEL) break;
        }
        if (b < 0) b = 0;
        g_bin[s] = (unsigned)b;
        g_kprime[s] = KSEL - (cum - sh[b]);
    }
}

// ---- 4. compact candidate keys: block-aggregated (ONE global atomic/block) -
__global__ __launch_bounds__(256) void compact_kernel(const float4* __restrict__ x) {
    __shared__ unsigned stage[8192];   // worst case: every element matches
    __shared__ unsigned s_cnt;
    __shared__ unsigned s_base;

    int s = blockIdx.y;
    unsigned bin = g_bin[s];
    int tid = threadIdx.x;
    if (tid == 0) s_cnt = 0;
    __syncthreads();

    const float4* p = x + (size_t)s * DIM4 + (size_t)blockIdx.x * 2048;
    #pragma unroll
    for (int it = 0; it < 8; it++) {
        float4 v = p[tid + it * 256];
        unsigned keys[4] = { f2key(v.x), f2key(v.y), f2key(v.z), f2key(v.w) };
        #pragma unroll
        for (int q = 0; q < 4; q++) {
            if ((keys[q] >> 21) == bin) {
                unsigned pos = atomicAdd(&s_cnt, 1u);   // smem atomic: cheap, rare
                stage[pos] = keys[q];
            }
        }
    }
    __syncthreads();

    unsigned cnt = s_cnt;
    if (tid == 0 && cnt) s_base = atomicAdd(&g_cnt[s], cnt);
    __syncthreads();

    if (cnt) {
        unsigned base = s_base;
        for (unsigned i = tid; i < cnt; i += 256) {
            unsigned pos = base + i;
            if (pos < CAP) g_cand[(size_t)s * CAP + pos] = stage[i];
        }
    }
}

// ---- 5. exact radix select over candidates (3 x 7-bit passes) --------------
__global__ __launch_bounds__(256) void select_kernel() {
    __shared__ unsigned sh[128];
    __shared__ unsigned s_prefix, s_kp;
    int s = blockIdx.x;
    int tid = threadIdx.x;
    unsigned n = g_cnt[s];
    if (n > CAP) n = CAP;
    unsigned prefix = g_bin[s] << 21;
    unsigned kp = g_kprime[s];

    #pragma unroll
    for (int pass = 0; pass < 3; pass++) {
        int shift = 14 - pass * 7;
        unsigned pmask = 0xFFFFFFFFu << (shift + 7);
        for (int i = tid; i < 128; i += 256) sh[i] = 0;
        __syncthreads();
        for (unsigned i = tid; i < n; i += 256) {
            unsigned key = g_cand[(size_t)s * CAP + i];
            if ((key & pmask) == prefix)
                atomicAdd(&sh[(key >> shift) & 127u], 1u);
        }
        __syncthreads();
        if (tid == 0) {
            unsigned cum = 0;
            int d = 127;
            for (; d >= 0; d--) {
                cum += sh[d];
                if (cum >= kp) break;
            }
            if (d < 0) d = 0;
            s_kp = kp - (cum - sh[d]);
            s_prefix = prefix | ((unsigned)d << shift);
        }
        __syncthreads();
        prefix = s_prefix;
        kp = s_kp;
        __syncthreads();
    }

    if (tid == 0) {
        unsigned key = prefix;
        unsigned u = (key & 0x80000000u) ? (key & 0x7FFFFFFFu) : ~key;
        g_thresh[s] = __uint_as_float(u);
    }
}

// ---- 6. masked transpose: (hw, c) -> (c, hw), fully coalesced --------------
__global__ __launch_bounds__(256) void mask_transpose_kernel(const float* __restrict__ x,
                                                             float* __restrict__ out) {
    __shared__ float tile[32][33];
    int b = blockIdx.z;
    float th = g_thresh[b];
    int c0 = blockIdx.x * 32;
    int hw0 = blockIdx.y * 32;
    const float* xin = x + (size_t)b * DIM;
    float* o = out + (size_t)b * DIM;
    int tx = threadIdx.x, ty = threadIdx.y;

    #pragma unroll
    for (int j = 0; j < 32; j += 8) {
        float v = xin[(size_t)(hw0 + ty + j) * C + (c0 + tx)];
        tile[ty + j][tx] = (v >= th) ? v : 0.0f;
    }
    __syncthreads();
    #pragma unroll
    for (int j = 0; j < 32; j += 8) {
        o[(size_t)(c0 + ty + j) * HW + (hw0 + tx)] = tile[tx][ty + j];
    }
}

// ---------------------------------------------------------------------------
extern "C" void kernel_launch(void* const* d_in, const int* in_sizes, int n_in,
                              void* d_out, int out_size) {
    (void)in_sizes; (void)n_in; (void)out_size;
    const float* x = (const float*)d_in[0];
    float* out = (float*)d_out;

    zero_kernel<<<(B * NBINS + 255) / 256, 256>>>();

    dim3 hgrid(HBLOCKS, B);
    hist_kernel<<<hgrid, 256>>>((const float4*)x);

    scan_kernel<<<B, 256>>>();

    compact_kernel<<<hgrid, 256>>>((const float4*)x);

    select_kernel<<<B, 256>>>();

    dim3 tblk(32, 8);
    dim3 tgrid(C / 32, HW / 32, B);
    mask_transpose_kernel<<<tgrid, tblk>>>(x, out);
}